// round 10
// baseline (speedup 1.0000x reference)
#include <cuda_runtime.h>
#include <cuda_bf16.h>
#include <cstdint>
#include <cstddef>

#define M_TOK 16384
#define DIM_D 1024
#define DIM_H 4096

// ---------------------------------------------------------------------------
// Scratch (device globals -- allocation-free rule)
// ---------------------------------------------------------------------------
__device__ int8_t g_xq [(size_t)M_TOK * DIM_D];          // 16 MB
__device__ int8_t g_w1q[(size_t)DIM_H * DIM_D];          // 4 MB
__device__ int8_t g_w2q[(size_t)DIM_D * DIM_H];          // 4 MB
__device__ float  g_h  [(size_t)M_TOK * DIM_H];          // 256 MB (gelu out, fp32)
__device__ int8_t g_hq [(size_t)M_TOK * DIM_H];          // 64 MB
__device__ unsigned int g_absmax[4];                     // x, w1, w2, gelu(h)

// ---------------------------------------------------------------------------
// PTX helpers (base sm_103-safe: mma.sync / ldmatrix / cp.async only)
// ---------------------------------------------------------------------------
__device__ __forceinline__ uint32_t smem_u32(const void* p) {
    uint32_t a;
    asm("{ .reg .u64 t; cvta.to.shared.u64 t, %1; cvt.u32.u64 %0, t; }"
        : "=r"(a) : "l"(p));
    return a;
}
#define LDSM4(r0, r1, r2, r3, addr) \
    asm volatile("ldmatrix.sync.aligned.m8n8.x4.shared.b16 {%0,%1,%2,%3}, [%4];" \
                 : "=r"(r0), "=r"(r1), "=r"(r2), "=r"(r3) : "r"(addr))
#define CPASYNC16(d, s) \
    asm volatile("cp.async.cg.shared.global [%0], [%1], 16;" \
                 :: "r"(d), "l"(s) : "memory")
#define CPCOMMIT() asm volatile("cp.async.commit_group;" ::: "memory")
#define CPWAIT(n)  asm volatile("cp.async.wait_group %0;" :: "n"(n) : "memory")

__device__ __forceinline__ void mma_s8(int* c, const uint32_t* a, const uint32_t* b) {
    asm volatile(
        "mma.sync.aligned.m16n8k32.row.col.s32.s8.s8.s32 "
        "{%0,%1,%2,%3}, {%4,%5,%6,%7}, {%8,%9}, {%0,%1,%2,%3};"
        : "+r"(c[0]), "+r"(c[1]), "+r"(c[2]), "+r"(c[3])
        : "r"(a[0]), "r"(a[1]), "r"(a[2]), "r"(a[3]), "r"(b[0]), "r"(b[1]));
}

// ---------------------------------------------------------------------------
// fused absmax (x, w1, w2 in one launch) + quantize
// ---------------------------------------------------------------------------
__global__ void init_absmax_kernel() {
    if (threadIdx.x < 4) g_absmax[threadIdx.x] = 0u;
}

__device__ __forceinline__ void absmax_body(const float4* s4, int n4,
                                            int b, int nb, int slot) {
    float m = 0.0f;
    for (int i = b * blockDim.x + threadIdx.x; i < n4; i += nb * blockDim.x) {
        float4 v = s4[i];
        m = fmaxf(m, fmaxf(fmaxf(fabsf(v.x), fabsf(v.y)),
                           fmaxf(fabsf(v.z), fabsf(v.w))));
    }
    #pragma unroll
    for (int o = 16; o > 0; o >>= 1)
        m = fmaxf(m, __shfl_xor_sync(0xffffffffu, m, o));
    if ((threadIdx.x & 31) == 0)
        atomicMax(&g_absmax[slot], __float_as_uint(m));
}

// grid = 4096 blocks: [0,2048) -> x, [2048,3072) -> w1, [3072,4096) -> w2
__global__ void absmax3_kernel(const float* __restrict__ x,
                               const float* __restrict__ w1,
                               const float* __restrict__ w2) {
    const int bx = blockIdx.x;
    if (bx < 2048)
        absmax_body((const float4*)x, M_TOK * DIM_D / 4, bx, 2048, 0);
    else if (bx < 3072)
        absmax_body((const float4*)w1, DIM_H * DIM_D / 4, bx - 2048, 1024, 1);
    else
        absmax_body((const float4*)w2, DIM_D * DIM_H / 4, bx - 3072, 1024, 2);
}

__device__ __forceinline__ void quant_body(const float4* s4, char4* d4, int n4,
                                           int b, int nb, int slot) {
    float am = __uint_as_float(g_absmax[slot]);
    float scale = fmaxf(am, 1e-8f) / 127.0f;
    for (int i = b * blockDim.x + threadIdx.x; i < n4; i += nb * blockDim.x) {
        float4 v = s4[i];
        float qx = fminf(fmaxf(rintf(v.x / scale), -127.0f), 127.0f);
        float qy = fminf(fmaxf(rintf(v.y / scale), -127.0f), 127.0f);
        float qz = fminf(fmaxf(rintf(v.z / scale), -127.0f), 127.0f);
        float qw = fminf(fmaxf(rintf(v.w / scale), -127.0f), 127.0f);
        d4[i] = make_char4((signed char)(int)qx, (signed char)(int)qy,
                           (signed char)(int)qz, (signed char)(int)qw);
    }
}

__global__ void quant3_kernel(const float* __restrict__ x,
                              const float* __restrict__ w1,
                              const float* __restrict__ w2) {
    const int bx = blockIdx.x;
    if (bx < 2048)
        quant_body((const float4*)x, (char4*)g_xq, M_TOK * DIM_D / 4, bx, 2048, 0);
    else if (bx < 3072)
        quant_body((const float4*)w1, (char4*)g_w1q, DIM_H * DIM_D / 4, bx - 2048, 1024, 1);
    else
        quant_body((const float4*)w2, (char4*)g_w2q, DIM_D * DIM_H / 4, bx - 3072, 1024, 2);
}

__global__ void quant_h_kernel(int n4) {
    float am = __uint_as_float(g_absmax[3]);
    float scale = fmaxf(am, 1e-8f) / 127.0f;
    const float4* s4 = (const float4*)g_h;
    char4* d4 = (char4*)g_hq;
    for (int i = blockIdx.x * blockDim.x + threadIdx.x; i < n4;
         i += gridDim.x * blockDim.x) {
        float4 v = s4[i];
        float qx = fminf(fmaxf(rintf(v.x / scale), -127.0f), 127.0f);
        float qy = fminf(fmaxf(rintf(v.y / scale), -127.0f), 127.0f);
        float qz = fminf(fmaxf(rintf(v.z / scale), -127.0f), 127.0f);
        float qw = fminf(fmaxf(rintf(v.w / scale), -127.0f), 127.0f);
        d4[i] = make_char4((signed char)(int)qx, (signed char)(int)qy,
                           (signed char)(int)qz, (signed char)(int)qw);
    }
}

// ---------------------------------------------------------------------------
// IMMA GEMM v2: C[M,Ng] = A[M,K] * B[Ng,K]^T (int8 K-major)
// CTA tile 128x256, 8 warps of 64x64, mma.m16n8k32, 4-stage cp.async.
// SMEM row stride 80B (conflict-free ldmatrix), one __syncthreads per chunk.
// ---------------------------------------------------------------------------
#define GELU_C 0.70710678118654752440f
#define SSTR 80
#define STAGES 4
#define ASZ (128 * SSTR)
#define BSZ (256 * SSTR)
#define GEMM_SMEM (STAGES * (ASZ + BSZ))   // 122880 B

template<int K, bool GELU>
__global__ void __launch_bounds__(256)
gemm_imma(const int8_t* __restrict__ A, const int8_t* __restrict__ B,
          const float* __restrict__ bias, float* __restrict__ Cout, int Ng,
          int slotA, int slotB) {
    extern __shared__ int8_t smem[];
    int8_t* smA = smem;
    int8_t* smB = smem + STAGES * ASZ;

    const int tid = threadIdx.x;
    const int wid = tid >> 5, lane = tid & 31;
    const int bm = blockIdx.y * 128, bn = blockIdx.x * 256;
    const int wm = (wid & 1) * 64, wn = (wid >> 1) * 64;
    constexpr int NCH = K / 64;

    int acc[4][8][4];
    #pragma unroll
    for (int i = 0; i < 4; i++)
        #pragma unroll
        for (int j = 0; j < 8; j++)
            #pragma unroll
            for (int r = 0; r < 4; r++) acc[i][j][r] = 0;

    auto issue = [&](int ch, int st) {
        const int k0 = ch * 64;
        int8_t* sa = smA + st * ASZ;
        int8_t* sb = smB + st * BSZ;
        #pragma unroll
        for (int it = 0; it < 2; it++) {            // A: 128 rows x 4 chunks
            int c = tid + it * 256;
            int row = c >> 2, c16 = (c & 3) << 4;
            CPASYNC16(smem_u32(&sa[row * SSTR + c16]),
                      A + (size_t)(bm + row) * K + k0 + c16);
        }
        #pragma unroll
        for (int it = 0; it < 4; it++) {            // B: 256 rows x 4 chunks
            int c = tid + it * 256;
            int row = c >> 2, c16 = (c & 3) << 4;
            CPASYNC16(smem_u32(&sb[row * SSTR + c16]),
                      B + (size_t)(bn + row) * K + k0 + c16);
        }
    };

    #pragma unroll
    for (int s = 0; s < STAGES - 1 && s < NCH; s++) { issue(s, s); CPCOMMIT(); }

    #pragma unroll 1
    for (int ch = 0; ch < NCH; ch++) {
        CPWAIT(STAGES - 2);
        __syncthreads();
        if (ch + STAGES - 1 < NCH) issue(ch + STAGES - 1, (ch + STAGES - 1) % STAGES);
        CPCOMMIT();

        const int st = ch % STAGES;
        const int8_t* sa = smA + st * ASZ;
        const int8_t* sb = smB + st * BSZ;
        const int r8 = lane & 7, mg = lane >> 3;

        #pragma unroll
        for (int ks = 0; ks < 2; ks++) {
            const int kb = ks * 32;
            uint32_t a[4][4];
            #pragma unroll
            for (int i = 0; i < 4; i++) {
                uint32_t addr = smem_u32(
                    &sa[(wm + i * 16 + (mg & 1) * 8 + r8) * SSTR + kb + (mg >> 1) * 16]);
                LDSM4(a[i][0], a[i][1], a[i][2], a[i][3], addr);
            }
            uint32_t b[8][2];
            #pragma unroll
            for (int jp = 0; jp < 4; jp++) {
                uint32_t addr = smem_u32(
                    &sb[(wn + jp * 16 + (mg >> 1) * 8 + r8) * SSTR + kb + (mg & 1) * 16]);
                uint32_t r0, r1, r2, r3;
                LDSM4(r0, r1, r2, r3, addr);
                b[jp * 2][0] = r0; b[jp * 2][1] = r1;
                b[jp * 2 + 1][0] = r2; b[jp * 2 + 1][1] = r3;
            }
            #pragma unroll
            for (int i = 0; i < 4; i++)
                #pragma unroll
                for (int j = 0; j < 8; j++)
                    mma_s8(acc[i][j], a[i], b[j]);
        }
    }

    // ---- epilogue: dequant + bias (+ exact gelu + absmax slot3) -> fp32 ----
    const float sA = fmaxf(__uint_as_float(g_absmax[slotA]), 1e-8f) / 127.0f;
    const float sB = fmaxf(__uint_as_float(g_absmax[slotB]), 1e-8f) / 127.0f;
    const float s = sA * sB;
    const int r4 = lane >> 2, c2 = (lane & 3) * 2;
    float lmax = 0.0f;

    #pragma unroll
    for (int i = 0; i < 4; i++) {
        const int row0 = bm + wm + i * 16 + r4;
        #pragma unroll
        for (int j = 0; j < 8; j++) {
            const int n = bn + wn + j * 8 + c2;
            const float b0 = __ldg(&bias[n]), b1 = __ldg(&bias[n + 1]);
            float v00 = (float)acc[i][j][0] * s + b0;
            float v01 = (float)acc[i][j][1] * s + b1;
            float v10 = (float)acc[i][j][2] * s + b0;
            float v11 = (float)acc[i][j][3] * s + b1;
            if (GELU) {
                v00 = 0.5f * v00 * (1.0f + erff(v00 * GELU_C));
                v01 = 0.5f * v01 * (1.0f + erff(v01 * GELU_C));
                v10 = 0.5f * v10 * (1.0f + erff(v10 * GELU_C));
                v11 = 0.5f * v11 * (1.0f + erff(v11 * GELU_C));
                lmax = fmaxf(lmax, fmaxf(fmaxf(fabsf(v00), fabsf(v01)),
                                         fmaxf(fabsf(v10), fabsf(v11))));
            }
            *(float2*)&Cout[(size_t)row0 * Ng + n]       = make_float2(v00, v01);
            *(float2*)&Cout[(size_t)(row0 + 8) * Ng + n] = make_float2(v10, v11);
        }
    }
    if (GELU) {
        #pragma unroll
        for (int o = 16; o > 0; o >>= 1)
            lmax = fmaxf(lmax, __shfl_xor_sync(0xffffffffu, lmax, o));
        if (lane == 0) atomicMax(&g_absmax[3], __float_as_uint(lmax));
    }
}

// ---------------------------------------------------------------------------
// launch
// ---------------------------------------------------------------------------
extern "C" void kernel_launch(void* const* d_in, const int* in_sizes, int n_in,
                              void* d_out, int out_size) {
    const float* x  = (const float*)d_in[0];
    const float* w1 = (const float*)d_in[1];
    const float* b1 = (const float*)d_in[2];
    const float* w2 = (const float*)d_in[3];
    const float* b2 = (const float*)d_in[4];
    float* out = (float*)d_out;

    const int nh = M_TOK * DIM_H;

    int8_t *d_xq, *d_w1q, *d_w2q, *d_hq;
    float* d_h;
    cudaGetSymbolAddress((void**)&d_xq,  g_xq);
    cudaGetSymbolAddress((void**)&d_w1q, g_w1q);
    cudaGetSymbolAddress((void**)&d_w2q, g_w2q);
    cudaGetSymbolAddress((void**)&d_hq,  g_hq);
    cudaGetSymbolAddress((void**)&d_h,   g_h);

    cudaFuncSetAttribute(gemm_imma<DIM_D, true>,
                         cudaFuncAttributeMaxDynamicSharedMemorySize, GEMM_SMEM);
    cudaFuncSetAttribute(gemm_imma<DIM_H, false>,
                         cudaFuncAttributeMaxDynamicSharedMemorySize, GEMM_SMEM);

    init_absmax_kernel<<<1, 32>>>();
    absmax3_kernel<<<4096, 256>>>(x, w1, w2);
    quant3_kernel<<<4096, 256>>>(x, w1, w2);

    // GEMM1: [16384,1024] x [4096,1024]^T -> +b1 -> gelu -> g_h, absmax slot3
    gemm_imma<DIM_D, true><<<dim3(DIM_H / 256, M_TOK / 128), 256, GEMM_SMEM>>>(
        d_xq, d_w1q, b1, d_h, DIM_H, 0, 1);

    quant_h_kernel<<<4096, 256>>>(nh / 4);

    // GEMM2: [16384,4096] x [1024,4096]^T -> +b2 -> out
    gemm_imma<DIM_H, false><<<dim3(DIM_D / 256, M_TOK / 128), 256, GEMM_SMEM>>>(
        d_hq, d_w2q, b2, out, DIM_D, 3, 2);
}

// round 11
// speedup vs baseline: 1.0384x; 1.0384x over previous
#include <cuda_runtime.h>
#include <cuda_bf16.h>
#include <cstdint>
#include <cstddef>

#define M_TOK 16384
#define DIM_D 1024
#define DIM_H 4096

// ---------------------------------------------------------------------------
// Scratch (device globals -- allocation-free rule)
// ---------------------------------------------------------------------------
__device__ int8_t g_xq [(size_t)M_TOK * DIM_D];          // 16 MB
__device__ int8_t g_w1q[(size_t)DIM_H * DIM_D];          // 4 MB
__device__ int8_t g_w2q[(size_t)DIM_D * DIM_H];          // 4 MB
__device__ float  g_h  [(size_t)M_TOK * DIM_H];          // 256 MB (gelu out, fp32)
__device__ int8_t g_hq [(size_t)M_TOK * DIM_H];          // 64 MB
__device__ unsigned int g_absmax[4];                     // x, w1, w2, gelu(h)

// ---------------------------------------------------------------------------
// PTX helpers (base sm_103-safe: mma.sync / ldmatrix / cp.async only)
// ---------------------------------------------------------------------------
__device__ __forceinline__ uint32_t smem_u32(const void* p) {
    uint32_t a;
    asm("{ .reg .u64 t; cvta.to.shared.u64 t, %1; cvt.u32.u64 %0, t; }"
        : "=r"(a) : "l"(p));
    return a;
}
#define LDSM4(r0, r1, r2, r3, addr) \
    asm volatile("ldmatrix.sync.aligned.m8n8.x4.shared.b16 {%0,%1,%2,%3}, [%4];" \
                 : "=r"(r0), "=r"(r1), "=r"(r2), "=r"(r3) : "r"(addr))
#define CPASYNC16(d, s) \
    asm volatile("cp.async.cg.shared.global [%0], [%1], 16;" \
                 :: "r"(d), "l"(s) : "memory")
#define CPCOMMIT() asm volatile("cp.async.commit_group;" ::: "memory")
#define CPWAIT(n)  asm volatile("cp.async.wait_group %0;" :: "n"(n) : "memory")

__device__ __forceinline__ void mma_s8(int* c, const uint32_t* a, const uint32_t* b) {
    asm volatile(
        "mma.sync.aligned.m16n8k32.row.col.s32.s8.s8.s32 "
        "{%0,%1,%2,%3}, {%4,%5,%6,%7}, {%8,%9}, {%0,%1,%2,%3};"
        : "+r"(c[0]), "+r"(c[1]), "+r"(c[2]), "+r"(c[3])
        : "r"(a[0]), "r"(a[1]), "r"(a[2]), "r"(a[3]), "r"(b[0]), "r"(b[1]));
}

// ---------------------------------------------------------------------------
// fused absmax (x, w1, w2) + quantize (numerics identical to passing kernels)
// ---------------------------------------------------------------------------
__global__ void init_absmax_kernel() {
    if (threadIdx.x < 4) g_absmax[threadIdx.x] = 0u;
}

__device__ __forceinline__ void absmax_body(const float4* s4, int n4,
                                            int b, int nb, int slot) {
    float m = 0.0f;
    for (int i = b * blockDim.x + threadIdx.x; i < n4; i += nb * blockDim.x) {
        float4 v = s4[i];
        m = fmaxf(m, fmaxf(fmaxf(fabsf(v.x), fabsf(v.y)),
                           fmaxf(fabsf(v.z), fabsf(v.w))));
    }
    #pragma unroll
    for (int o = 16; o > 0; o >>= 1)
        m = fmaxf(m, __shfl_xor_sync(0xffffffffu, m, o));
    if ((threadIdx.x & 31) == 0)
        atomicMax(&g_absmax[slot], __float_as_uint(m));
}

__global__ void absmax3_kernel(const float* __restrict__ x,
                               const float* __restrict__ w1,
                               const float* __restrict__ w2) {
    const int bx = blockIdx.x;
    if (bx < 2048)
        absmax_body((const float4*)x, M_TOK * DIM_D / 4, bx, 2048, 0);
    else if (bx < 3072)
        absmax_body((const float4*)w1, DIM_H * DIM_D / 4, bx - 2048, 1024, 1);
    else
        absmax_body((const float4*)w2, DIM_D * DIM_H / 4, bx - 3072, 1024, 2);
}

__device__ __forceinline__ void quant_body(const float4* s4, char4* d4, int n4,
                                           int b, int nb, int slot) {
    float am = __uint_as_float(g_absmax[slot]);
    float scale = fmaxf(am, 1e-8f) / 127.0f;
    for (int i = b * blockDim.x + threadIdx.x; i < n4; i += nb * blockDim.x) {
        float4 v = s4[i];
        float qx = fminf(fmaxf(rintf(v.x / scale), -127.0f), 127.0f);
        float qy = fminf(fmaxf(rintf(v.y / scale), -127.0f), 127.0f);
        float qz = fminf(fmaxf(rintf(v.z / scale), -127.0f), 127.0f);
        float qw = fminf(fmaxf(rintf(v.w / scale), -127.0f), 127.0f);
        d4[i] = make_char4((signed char)(int)qx, (signed char)(int)qy,
                           (signed char)(int)qz, (signed char)(int)qw);
    }
}

__global__ void quant3_kernel(const float* __restrict__ x,
                              const float* __restrict__ w1,
                              const float* __restrict__ w2) {
    const int bx = blockIdx.x;
    if (bx < 2048)
        quant_body((const float4*)x, (char4*)g_xq, M_TOK * DIM_D / 4, bx, 2048, 0);
    else if (bx < 3072)
        quant_body((const float4*)w1, (char4*)g_w1q, DIM_H * DIM_D / 4, bx - 2048, 1024, 1);
    else
        quant_body((const float4*)w2, (char4*)g_w2q, DIM_D * DIM_H / 4, bx - 3072, 1024, 2);
}

__global__ void quant_h_kernel(int n4) {
    float am = __uint_as_float(g_absmax[3]);
    float scale = fmaxf(am, 1e-8f) / 127.0f;
    const float4* s4 = (const float4*)g_h;
    char4* d4 = (char4*)g_hq;
    for (int i = blockIdx.x * blockDim.x + threadIdx.x; i < n4;
         i += gridDim.x * blockDim.x) {
        float4 v = s4[i];
        float qx = fminf(fmaxf(rintf(v.x / scale), -127.0f), 127.0f);
        float qy = fminf(fmaxf(rintf(v.y / scale), -127.0f), 127.0f);
        float qz = fminf(fmaxf(rintf(v.z / scale), -127.0f), 127.0f);
        float qw = fminf(fmaxf(rintf(v.w / scale), -127.0f), 127.0f);
        d4[i] = make_char4((signed char)(int)qx, (signed char)(int)qy,
                           (signed char)(int)qz, (signed char)(int)qw);
    }
}

// ---------------------------------------------------------------------------
// HYBRID GEMM: C[M,Ng] = A[M,K] * B[Ng,K]^T (int8 K-major)
// CTA tile 256x128, 512 threads.
//   warps 0-7  : IMMA (tensor pipe)  -> rows [0,128)   of the tile
//   warps 8-15 : dp4a (ALU pipe)     -> rows [128,256) of the tile
// Shared B tile (128 x 64B, row stride 80B), A tile 256 rows.
// 3-stage cp.async pipeline, one __syncthreads per 64-K chunk.
// ---------------------------------------------------------------------------
#define GELU_C 0.70710678118654752440f
#define HSTR   80
#define HST_A  0
#define HST_B  (256 * HSTR)                 // 20480
#define HST_SZ (256 * HSTR + 128 * HSTR)    // 30720 per stage
#define HSTAGES 3
#define HSMEM  (HSTAGES * HST_SZ)           // 92160 B

template<int K, bool GELU>
__global__ void __launch_bounds__(512)
gemm_hybrid(const int8_t* __restrict__ A, const int8_t* __restrict__ B,
            const float* __restrict__ bias, float* __restrict__ Cout, int Ng,
            int slotA, int slotB) {
    extern __shared__ int8_t smem[];

    const int tid = threadIdx.x;
    const int wid = tid >> 5, lane = tid & 31;
    const int bm = blockIdx.y * 256, bn = blockIdx.x * 128;
    constexpr int NCH = K / 64;

    // loader: 1536 x 16B per stage over 512 threads (A: 1024 ops, B: 512 ops)
    auto issue = [&](int ch, int st) {
        const int k0 = ch * 64;
        int8_t* sg = smem + st * HST_SZ;
        #pragma unroll
        for (int it = 0; it < 3; it++) {
            int o = tid + it * 512;
            if (o < 1024) {                 // A rows 0..255
                int row = o >> 2, c16 = (o & 3) << 4;
                CPASYNC16(smem_u32(&sg[HST_A + row * HSTR + c16]),
                          A + (size_t)(bm + row) * K + k0 + c16);
            } else {                        // B rows 0..127
                int o2 = o - 1024;
                int row = o2 >> 2, c16 = (o2 & 3) << 4;
                CPASYNC16(smem_u32(&sg[HST_B + row * HSTR + c16]),
                          B + (size_t)(bn + row) * K + k0 + c16);
            }
        }
    };

    // --- accumulators (per-branch; compiler keeps the live set per warp) ---
    int iacc[4][4][4];                       // IMMA warps
    int dacc[8][8];                          // dp4a warps
    if (wid < 8) {
        #pragma unroll
        for (int i = 0; i < 4; i++)
            #pragma unroll
            for (int j = 0; j < 4; j++)
                #pragma unroll
                for (int r = 0; r < 4; r++) iacc[i][j][r] = 0;
    } else {
        #pragma unroll
        for (int i = 0; i < 8; i++)
            #pragma unroll
            for (int j = 0; j < 8; j++) dacc[i][j] = 0;
    }

    #pragma unroll
    for (int s = 0; s < HSTAGES - 1; s++) { issue(s, s); CPCOMMIT(); }

    const int wm = (wid & 1) * 64, wn = ((wid >> 1) & 3) * 32;  // IMMA subtile
    const int dt = tid - 256;                                    // dp4a thread id
    const int tx = dt & 15, ty = dt >> 4;                        // dp4a mapping

    #pragma unroll 1
    for (int ch = 0; ch < NCH; ch++) {
        CPWAIT(HSTAGES - 2);
        __syncthreads();
        if (ch + HSTAGES - 1 < NCH) issue(ch + HSTAGES - 1, (ch + HSTAGES - 1) % HSTAGES);
        CPCOMMIT();

        const int8_t* sg = smem + (ch % HSTAGES) * HST_SZ;

        if (wid < 8) {
            // ---------------- IMMA half: rows [0,128) ----------------
            const int8_t* sa = sg + HST_A;
            const int8_t* sb = sg + HST_B;
            const int r8 = lane & 7, mg = lane >> 3;
            #pragma unroll
            for (int ks = 0; ks < 2; ks++) {
                const int kb = ks * 32;
                uint32_t a[4][4];
                #pragma unroll
                for (int i = 0; i < 4; i++) {
                    uint32_t addr = smem_u32(
                        &sa[(wm + i * 16 + (mg & 1) * 8 + r8) * HSTR + kb + (mg >> 1) * 16]);
                    LDSM4(a[i][0], a[i][1], a[i][2], a[i][3], addr);
                }
                uint32_t b[4][2];
                #pragma unroll
                for (int jp = 0; jp < 2; jp++) {
                    uint32_t addr = smem_u32(
                        &sb[(wn + jp * 16 + (mg >> 1) * 8 + r8) * HSTR + kb + (mg & 1) * 16]);
                    uint32_t r0, r1, r2, r3;
                    LDSM4(r0, r1, r2, r3, addr);
                    b[jp * 2][0] = r0; b[jp * 2][1] = r1;
                    b[jp * 2 + 1][0] = r2; b[jp * 2 + 1][1] = r3;
                }
                #pragma unroll
                for (int i = 0; i < 4; i++)
                    #pragma unroll
                    for (int j = 0; j < 4; j++)
                        mma_s8(iacc[i][j], a[i], b[j]);
            }
        } else {
            // ---------------- dp4a half: rows [128,256) ----------------
            // thread covers m = 128+ty*8+i (i<8), n = j*16+tx (j<8)
            const int8_t* sa = sg + HST_A + (128 + ty * 8) * HSTR;
            const int8_t* sb = sg + HST_B + tx * HSTR;
            #pragma unroll
            for (int k16 = 0; k16 < 4; k16++) {
                int4 bf[8];
                #pragma unroll
                for (int j = 0; j < 8; j++)
                    bf[j] = *(const int4*)&sb[j * 16 * HSTR + k16 * 16];
                #pragma unroll
                for (int i = 0; i < 8; i++) {
                    int4 af = *(const int4*)&sa[i * HSTR + k16 * 16];
                    #pragma unroll
                    for (int j = 0; j < 8; j++) {
                        int c = dacc[i][j];
                        c = __dp4a(af.x, bf[j].x, c);
                        c = __dp4a(af.y, bf[j].y, c);
                        c = __dp4a(af.z, bf[j].z, c);
                        c = __dp4a(af.w, bf[j].w, c);
                        dacc[i][j] = c;
                    }
                }
            }
        }
    }

    // ---- epilogue: dequant + bias (+ exact gelu + absmax slot3) -> fp32 ----
    const float sA = fmaxf(__uint_as_float(g_absmax[slotA]), 1e-8f) / 127.0f;
    const float sB = fmaxf(__uint_as_float(g_absmax[slotB]), 1e-8f) / 127.0f;
    const float s = sA * sB;
    float lmax = 0.0f;

    if (wid < 8) {
        const int r4 = lane >> 2, c2 = (lane & 3) * 2;
        #pragma unroll
        for (int i = 0; i < 4; i++) {
            const int row0 = bm + wm + i * 16 + r4;
            #pragma unroll
            for (int j = 0; j < 4; j++) {
                const int n = bn + wn + j * 8 + c2;
                const float b0 = __ldg(&bias[n]), b1 = __ldg(&bias[n + 1]);
                float v00 = (float)iacc[i][j][0] * s + b0;
                float v01 = (float)iacc[i][j][1] * s + b1;
                float v10 = (float)iacc[i][j][2] * s + b0;
                float v11 = (float)iacc[i][j][3] * s + b1;
                if (GELU) {
                    v00 = 0.5f * v00 * (1.0f + erff(v00 * GELU_C));
                    v01 = 0.5f * v01 * (1.0f + erff(v01 * GELU_C));
                    v10 = 0.5f * v10 * (1.0f + erff(v10 * GELU_C));
                    v11 = 0.5f * v11 * (1.0f + erff(v11 * GELU_C));
                    lmax = fmaxf(lmax, fmaxf(fmaxf(fabsf(v00), fabsf(v01)),
                                             fmaxf(fabsf(v10), fabsf(v11))));
                }
                *(float2*)&Cout[(size_t)row0 * Ng + n]       = make_float2(v00, v01);
                *(float2*)&Cout[(size_t)(row0 + 8) * Ng + n] = make_float2(v10, v11);
            }
        }
    } else {
        float bb[8];
        #pragma unroll
        for (int j = 0; j < 8; j++) bb[j] = __ldg(&bias[bn + j * 16 + tx]);
        #pragma unroll
        for (int i = 0; i < 8; i++) {
            const int row = bm + 128 + ty * 8 + i;
            #pragma unroll
            for (int j = 0; j < 8; j++) {
                float v = (float)dacc[i][j] * s + bb[j];
                if (GELU) {
                    v = 0.5f * v * (1.0f + erff(v * GELU_C));
                    lmax = fmaxf(lmax, fabsf(v));
                }
                Cout[(size_t)row * Ng + bn + j * 16 + tx] = v;
            }
        }
    }
    if (GELU) {
        #pragma unroll
        for (int o = 16; o > 0; o >>= 1)
            lmax = fmaxf(lmax, __shfl_xor_sync(0xffffffffu, lmax, o));
        if (lane == 0) atomicMax(&g_absmax[3], __float_as_uint(lmax));
    }
}

// ---------------------------------------------------------------------------
// launch
// ---------------------------------------------------------------------------
extern "C" void kernel_launch(void* const* d_in, const int* in_sizes, int n_in,
                              void* d_out, int out_size) {
    const float* x  = (const float*)d_in[0];
    const float* w1 = (const float*)d_in[1];
    const float* b1 = (const float*)d_in[2];
    const float* w2 = (const float*)d_in[3];
    const float* b2 = (const float*)d_in[4];
    float* out = (float*)d_out;

    const int nh = M_TOK * DIM_H;

    int8_t *d_xq, *d_w1q, *d_w2q, *d_hq;
    float* d_h;
    cudaGetSymbolAddress((void**)&d_xq,  g_xq);
    cudaGetSymbolAddress((void**)&d_w1q, g_w1q);
    cudaGetSymbolAddress((void**)&d_w2q, g_w2q);
    cudaGetSymbolAddress((void**)&d_hq,  g_hq);
    cudaGetSymbolAddress((void**)&d_h,   g_h);

    cudaFuncSetAttribute(gemm_hybrid<DIM_D, true>,
                         cudaFuncAttributeMaxDynamicSharedMemorySize, HSMEM);
    cudaFuncSetAttribute(gemm_hybrid<DIM_H, false>,
                         cudaFuncAttributeMaxDynamicSharedMemorySize, HSMEM);

    init_absmax_kernel<<<1, 32>>>();
    absmax3_kernel<<<4096, 256>>>(x, w1, w2);
    quant3_kernel<<<4096, 256>>>(x, w1, w2);

    // GEMM1: [16384,1024] x [4096,1024]^T -> +b1 -> gelu -> g_h, absmax slot3
    gemm_hybrid<DIM_D, true><<<dim3(DIM_H / 128, M_TOK / 256), 512, HSMEM>>>(
        d_xq, d_w1q, b1, d_h, DIM_H, 0, 1);

    quant_h_kernel<<<4096, 256>>>(nh / 4);

    // GEMM2: [16384,4096] x [1024,4096]^T -> +b2 -> out
    gemm_hybrid<DIM_H, false><<<dim3(DIM_D / 128, M_TOK / 256), 512, HSMEM>>>(
        d_hq, d_w2q, b2, out, DIM_D, 3, 2);
}